// round 7
// baseline (speedup 1.0000x reference)
#include <cuda_runtime.h>
#include <cuda_bf16.h>
#include <cstdint>

// ---------------- shapes ----------------
#define NTOK 4096
#define CDIM 1024
#define NEXP 64
#define TOPK 8
#define CAP  1024
#define HS   1024
#define HE   512

// ---------------- helpers ----------------
__device__ __forceinline__ uint32_t smem_u32(const void* p) {
    uint32_t a;
    asm("{ .reg .u64 t; cvta.to.shared.u64 t, %1; cvt.u32.u64 %0, t; }" : "=r"(a) : "l"(p));
    return a;
}
#define CP_ASYNC16(dst, src) \
    asm volatile("cp.async.cg.shared.global [%0], [%1], 16;" :: "r"(dst), "l"(src))
#define CP_COMMIT() asm volatile("cp.async.commit_group;" ::: "memory")
#define CP_WAIT2()  asm volatile("cp.async.wait_group 2;" ::: "memory")

__device__ __forceinline__ void ldm_x4(uint32_t* r, uint32_t addr) {
    asm volatile("ldmatrix.sync.aligned.m8n8.x4.shared.b16 {%0,%1,%2,%3}, [%4];"
        : "=r"(r[0]), "=r"(r[1]), "=r"(r[2]), "=r"(r[3]) : "r"(addr));
}
__device__ __forceinline__ void mma_tf32(float* d, const uint32_t* a, const uint32_t* b) {
    asm volatile(
        "mma.sync.aligned.m16n8k8.row.col.f32.tf32.tf32.f32 "
        "{%0,%1,%2,%3}, {%4,%5,%6,%7}, {%8,%9}, {%0,%1,%2,%3};"
        : "+f"(d[0]), "+f"(d[1]), "+f"(d[2]), "+f"(d[3])
        : "r"(a[0]), "r"(a[1]), "r"(a[2]), "r"(a[3]), "r"(b[0]), "r"(b[1]));
}
__device__ __forceinline__ float to_tf32(float v) {
    uint32_t r;
    asm("cvt.rna.tf32.f32 %0, %1;" : "=r"(r) : "f"(v));
    return __uint_as_float(r);
}

// ---------------- scratch (device globals) ----------------
__device__ float g_xr  [(size_t)NTOK * CDIM];
__device__ float g_sh  [(size_t)NTOK * HS];
__device__ float g_eh  [(size_t)NEXP * CAP * HE];
__device__ float g_eoe [(size_t)NEXP * CAP * CDIM];
__device__ float g_supt[(size_t)(2 * HS) * CDIM];
__device__ float g_sdnt[(size_t)CDIM * HS];
__device__ float g_eupt[(size_t)NEXP * (2 * HE) * CDIM];
__device__ float g_ednt[(size_t)NEXP * CDIM * HE];
__device__ int   g_counts[NEXP];
__device__ int   g_rowidx[NEXP * CAP];
__device__ int   g_slots[NTOK * TOPK];
__device__ float g_wts [NTOK * TOPK];

// ---------------- small kernels ----------------
__global__ void zero_counts_kernel(int* counts) {
    if (threadIdx.x < NEXP) counts[threadIdx.x] = 0;
}

// transpose + tf32-round: in [K][N] fp32 -> out [N][K] fp32(tf32).
// If half>0, output rows (y,g)-interleaved: n<half -> 2n ; else 2(n-half)+1.
__global__ void transpose_round_kernel(const float* __restrict__ in, float* __restrict__ o,
                                       int K, int N, long inz, long outz, int half) {
    __shared__ float tile[32][33];
    int z = blockIdx.z;
    in += (size_t)z * inz; o += (size_t)z * outz;
    int n0 = blockIdx.x * 32, k0 = blockIdx.y * 32;
    int tx = threadIdx.x, ty = threadIdx.y;
    #pragma unroll
    for (int i = 0; i < 32; i += 8)
        tile[ty + i][tx] = in[(size_t)(k0 + ty + i) * N + n0 + tx];
    __syncthreads();
    #pragma unroll
    for (int i = 0; i < 32; i += 8) {
        float v = tile[tx][ty + i];
        int n = n0 + ty + i;
        int nout = (half > 0) ? ((n < half) ? 2 * n : 2 * (n - half) + 1) : n;
        o[(size_t)nout * K + k0 + tx] = to_tf32(v);
    }
}

// ---------------- router ----------------
__global__ __launch_bounds__(256) void router_kernel(
    const float* __restrict__ x, const float* __restrict__ rw, const float* __restrict__ bias,
    int* __restrict__ counts, int* __restrict__ rowidx,
    int* __restrict__ slots, float* __restrict__ wts, float* __restrict__ xr) {
    int t = blockIdx.x;
    int tid = threadIdx.x;
    __shared__ float xs[CDIM];
    __shared__ float partial[256];
    __shared__ float sc[NEXP];
    __shared__ float sb[NEXP];

    for (int i = tid; i < CDIM; i += 256) xs[i] = x[(size_t)t * CDIM + i];
    __syncthreads();

    int e = tid & 63, part = tid >> 6;
    float acc = 0.f;
    const float* rwp = rw + (size_t)(part * 256) * NEXP + e;
    #pragma unroll 8
    for (int c = 0; c < 256; c++) acc += xs[part * 256 + c] * rwp[(size_t)c * NEXP];
    partial[tid] = acc;
    __syncthreads();
    if (tid < NEXP) {
        float v = partial[tid] + partial[tid + 64] + partial[tid + 128] + partial[tid + 192];
        float s = 1.f / (1.f + __expf(-v));
        sc[tid] = s;
        sb[tid] = s + bias[tid];
    }
    __syncthreads();

    if (tid == 0) {
        float wsum = 0.f;
        int eid[TOPK]; float ww[TOPK];
        #pragma unroll
        for (int k = 0; k < TOPK; k++) {
            int best = 0; float bv = sb[0];
            for (int i = 1; i < NEXP; i++) { float v = sb[i]; if (v > bv) { bv = v; best = i; } }
            sb[best] = -1e30f;
            eid[k] = best; ww[k] = sc[best]; wsum += sc[best];
        }
        float inv = 1.f / wsum;
        #pragma unroll
        for (int k = 0; k < TOPK; k++) {
            int pos  = atomicAdd(&counts[eid[k]], 1);
            int slot = eid[k] * CAP + pos;
            rowidx[slot] = t;
            slots[t * TOPK + k] = slot;
            wts  [t * TOPK + k] = ww[k] * inv;
        }
    }

    for (int i = tid; i < CDIM; i += 256)
        xr[(size_t)t * CDIM + i] = to_tf32(xs[i]);
}

// ---------------- tf32 mma.sync GEMM: D[M,N] = A[M,K] @ Bt[N,K]^T ----------------
// CTA tile 128Mx256N, 8 warps of 64x64, Kc=32, 4-stage single-sync cp.async pipeline.
// Smem: A 128x144B = 18432, B 256x144B = 36864; stage = 55296; 4 stages = 221184.
#define ROWB 144
#define A_BYTES 18432
#define STG_BYTES 55296

__device__ __forceinline__ void issue_stage(
    uint32_t sdst, const float* __restrict__ pA, const float* __restrict__ pB,
    int K, int kcol, int tid, const int* ar) {
    #pragma unroll
    for (int i = 0; i < 4; i++) {
        int id = tid + 256 * i;
        int row = id >> 3, c4 = id & 7;
        uint32_t so = (uint32_t)(row * ROWB + c4 * 16);
        CP_ASYNC16(sdst + so, pA + (size_t)ar[i] * K + kcol + c4 * 4);
    }
    #pragma unroll
    for (int i = 0; i < 8; i++) {
        int id = tid + 256 * i;
        int row = id >> 3, c4 = id & 7;
        uint32_t so = (uint32_t)(row * ROWB + c4 * 16);
        CP_ASYNC16(sdst + A_BYTES + so, pB + (size_t)row * K + kcol + c4 * 4);
    }
}

__global__ __launch_bounds__(256, 1) void gemm_kernel(
    const float* __restrict__ A, const float* __restrict__ B,
    float* __restrict__ D, float* __restrict__ H,
    int M, int N, int K,
    long sAz, long sBz, long sDz,
    const int* __restrict__ counts, const int* __restrict__ rowidx) {
    extern __shared__ __align__(128) char smem[];
    int z = blockIdx.z;
    if (counts) M = counts[z];
    int m0 = blockIdx.y * 128;
    if (m0 >= M) return;
    int n0 = blockIdx.x * 256;
    A += (size_t)z * sAz; B += (size_t)z * sBz;

    int tid = threadIdx.x, wid = tid >> 5, lane = tid & 31;
    int wm = (wid & 1) * 64;
    int wn = (wid >> 1) * 64;
    uint32_t sbase = smem_u32(smem);

    const float* pA;
    int ar[4];
    if (rowidx) {
        const int* ridx = rowidx + (size_t)z * CAP + m0;
        pA = A;
        #pragma unroll
        for (int i = 0; i < 4; i++) ar[i] = ridx[(tid >> 3) + 32 * i];
    } else {
        pA = A + (size_t)m0 * K;
        #pragma unroll
        for (int i = 0; i < 4; i++) ar[i] = (tid >> 3) + 32 * i;
    }
    const float* pB = B + (size_t)n0 * K;

    float acc[4][8][4];
    #pragma unroll
    for (int i = 0; i < 4; i++)
        #pragma unroll
        for (int j = 0; j < 8; j++)
            #pragma unroll
            for (int r = 0; r < 4; r++) acc[i][j][r] = 0.f;

    const int nk = K >> 5;   // >= 16 for all our K
    issue_stage(sbase,                 pA, pB, K, 0,  tid, ar); CP_COMMIT();
    issue_stage(sbase + STG_BYTES,     pA, pB, K, 32, tid, ar); CP_COMMIT();
    issue_stage(sbase + 2 * STG_BYTES, pA, pB, K, 64, tid, ar); CP_COMMIT();

    int laneA_row = lane & 15;
    int laneA_c   = ((lane >> 4) & 1) * 16;
    int laneB_n   = (lane & 7) + ((lane >> 4) & 1) * 8;
    int laneB_c   = ((lane >> 3) & 1) * 16;

    for (int kc = 0; kc < nk; kc++) {
        CP_WAIT2();            // stage kc resident
        __syncthreads();       // all warps done reading stage (kc-1)%4 == (kc+3)%4
        if (kc + 3 < nk)
            issue_stage(sbase + ((kc + 3) & 3) * STG_BYTES, pA, pB, K, (kc + 3) * 32, tid, ar);
        CP_COMMIT();           // (empty groups at tail keep the count consistent)

        uint32_t sA = sbase + (kc & 3) * STG_BYTES;
        uint32_t sB = sA + A_BYTES;
        #pragma unroll
        for (int s = 0; s < 4; s++) {
            uint32_t a[4][4];
            #pragma unroll
            for (int mi = 0; mi < 4; mi++)
                ldm_x4(a[mi], sA + (uint32_t)((wm + mi * 16 + laneA_row) * ROWB + s * 32 + laneA_c));
            #pragma unroll
            for (int j = 0; j < 4; j++) {
                uint32_t rb[4];
                ldm_x4(rb, sB + (uint32_t)((wn + j * 16 + laneB_n) * ROWB + s * 32 + laneB_c));
                #pragma unroll
                for (int mi = 0; mi < 4; mi++) {
                    mma_tf32(acc[mi][2 * j],     a[mi], rb);
                    mma_tf32(acc[mi][2 * j + 1], a[mi], rb + 2);
                }
            }
        }
    }

    int r0 = lane >> 2, c0 = (lane & 3) * 2;
    if (H) {
        // fused SwiGLU epilogue: cols (y,g) interleaved -> h = silu(g)*y, tf32-rounded
        int halfN = N >> 1;
        H += (size_t)z * sDz;
        #pragma unroll
        for (int mi = 0; mi < 4; mi++) {
            #pragma unroll
            for (int ni = 0; ni < 8; ni++) {
                int row = m0 + wm + mi * 16 + r0;
                int p = (n0 + wn + ni * 8 + c0) >> 1;
                float y0 = acc[mi][ni][0], gg0 = acc[mi][ni][1];
                float y1 = acc[mi][ni][2], gg1 = acc[mi][ni][3];
                H[(size_t)row * halfN + p]       = to_tf32(y0 * gg0 / (1.f + __expf(-gg0)));
                H[(size_t)(row + 8) * halfN + p] = to_tf32(y1 * gg1 / (1.f + __expf(-gg1)));
            }
        }
    } else {
        D += (size_t)z * sDz;
        #pragma unroll
        for (int mi = 0; mi < 4; mi++) {
            #pragma unroll
            for (int ni = 0; ni < 8; ni++) {
                int row = m0 + wm + mi * 16 + r0;
                int col = n0 + wn + ni * 8 + c0;
                *(float2*)(D + (size_t)row * N + col) = make_float2(acc[mi][ni][0], acc[mi][ni][1]);
                *(float2*)(D + (size_t)(row + 8) * N + col) = make_float2(acc[mi][ni][2], acc[mi][ni][3]);
            }
        }
    }
}

// ---------------- combine ----------------
__global__ __launch_bounds__(256) void combine_kernel(
    const float* __restrict__ oe, const int* __restrict__ slots,
    const float* __restrict__ wts, float* __restrict__ out) {
    int t = blockIdx.x;
    int c = threadIdx.x * 4;
    int sl[TOPK]; float ww[TOPK];
    #pragma unroll
    for (int k = 0; k < TOPK; k++) { sl[k] = slots[t * TOPK + k]; ww[k] = wts[t * TOPK + k]; }
    float4 acc = *(float4*)(out + (size_t)t * CDIM + c);
    #pragma unroll
    for (int k = 0; k < TOPK; k++) {
        float4 v = *(const float4*)(oe + (size_t)sl[k] * CDIM + c);
        acc.x += ww[k] * v.x; acc.y += ww[k] * v.y;
        acc.z += ww[k] * v.z; acc.w += ww[k] * v.w;
    }
    *(float4*)(out + (size_t)t * CDIM + c) = acc;
}

// ---------------- launch ----------------
extern "C" void kernel_launch(void* const* d_in, const int* in_sizes, int n_in,
                              void* d_out, int out_size) {
    const float* x       = (const float*)d_in[0];
    const float* rw      = (const float*)d_in[1];
    const float* bias    = (const float*)d_in[2];
    const float* sup_w   = (const float*)d_in[3];
    const float* sdown_w = (const float*)d_in[4];
    const float* eup_w   = (const float*)d_in[5];
    const float* edown_w = (const float*)d_in[6];
    float* out = (float*)d_out;
    (void)in_sizes; (void)n_in; (void)out_size;

    float *xr, *sh, *eh, *eoe, *supt, *sdnt, *eupt, *ednt, *wts;
    int *counts, *rowidx, *slots;
    cudaGetSymbolAddress((void**)&xr, g_xr);
    cudaGetSymbolAddress((void**)&sh, g_sh);
    cudaGetSymbolAddress((void**)&eh, g_eh);
    cudaGetSymbolAddress((void**)&eoe, g_eoe);
    cudaGetSymbolAddress((void**)&supt, g_supt);
    cudaGetSymbolAddress((void**)&sdnt, g_sdnt);
    cudaGetSymbolAddress((void**)&eupt, g_eupt);
    cudaGetSymbolAddress((void**)&ednt, g_ednt);
    cudaGetSymbolAddress((void**)&counts, g_counts);
    cudaGetSymbolAddress((void**)&rowidx, g_rowidx);
    cudaGetSymbolAddress((void**)&slots, g_slots);
    cudaGetSymbolAddress((void**)&wts, g_wts);

    cudaFuncSetAttribute(gemm_kernel, cudaFuncAttributeMaxDynamicSharedMemorySize, 4 * STG_BYTES);
    const int gsmem = 4 * STG_BYTES;

    // 1. routing (writes xr + rowidx)
    zero_counts_kernel<<<1, 64>>>(counts);
    router_kernel<<<NTOK, 256>>>(x, rw, bias, counts, rowidx, slots, wts, xr);

    // 2. weight prep (transpose + tf32 round; up weights (y,g)-interleaved)
    transpose_round_kernel<<<dim3(2 * HS / 32, CDIM / 32, 1), dim3(32, 8)>>>(
        sup_w, supt, CDIM, 2 * HS, 0, 0, HS);
    transpose_round_kernel<<<dim3(CDIM / 32, HS / 32, 1), dim3(32, 8)>>>(
        sdown_w, sdnt, HS, CDIM, 0, 0, 0);
    transpose_round_kernel<<<dim3(2 * HE / 32, CDIM / 32, NEXP), dim3(32, 8)>>>(
        eup_w, eupt, CDIM, 2 * HE, (long)CDIM * 2 * HE, (long)2 * HE * CDIM, HE);
    transpose_round_kernel<<<dim3(CDIM / 32, HE / 32, NEXP), dim3(32, 8)>>>(
        edown_w, ednt, HE, CDIM, (long)HE * CDIM, (long)CDIM * HE, 0);

    // 3. shared expert: up(+swiglu fused) -> down
    gemm_kernel<<<dim3(2 * HS / 256, NTOK / 128, 1), 256, gsmem>>>(
        xr, supt, nullptr, sh, NTOK, 2 * HS, CDIM, 0, 0, 0, nullptr, nullptr);
    gemm_kernel<<<dim3(CDIM / 256, NTOK / 128, 1), 256, gsmem>>>(
        sh, sdnt, out, nullptr, NTOK, CDIM, HS, 0, 0, 0, nullptr, nullptr);

    // 4. expert grouped GEMMs: up(gather A + swiglu fused) -> down
    gemm_kernel<<<dim3(2 * HE / 256, CAP / 128, NEXP), 256, gsmem>>>(
        xr, eupt, nullptr, eh, CAP, 2 * HE, CDIM,
        0, (long)(2 * HE) * CDIM, (long)CAP * HE, counts, rowidx);
    gemm_kernel<<<dim3(CDIM / 256, CAP / 128, NEXP), 256, gsmem>>>(
        eh, ednt, eoe, nullptr, CAP, CDIM, HE,
        (long)CAP * HE, (long)CDIM * HE, (long)CAP * CDIM, counts, nullptr);

    // 5. combine
    combine_kernel<<<NTOK, 256>>>(eoe, slots, wts, out);
}